// round 1
// baseline (speedup 1.0000x reference)
#include <cuda_runtime.h>
#include <math.h>

// Problem dims
#define NT 4096   // B*S tokens
#define HD 896    // hidden
#define ID 4864   // intermediate
#define NE 4      // experts
// GEMM tiling
#define BM 128
#define BN 64
#define BK 16
#define TM 8
#define TN 4

// ---------------- scratch (device globals; no allocation in kernel_launch) ----------------
__device__ int   g_cnt[NE];
__device__ int   g_tok[NE][NT];
__device__ float g_wt[NE][NT];
__device__ int   g_slot[NT][2];
__device__ float g_h[(size_t)NE * NT * ID];   // silu(xG^T)*(xU^T)*w, per (expert, local slot)
__device__ float g_y[(size_t)NE * NT * HD];   // down-projected rows per (expert, local slot)

// ---------------- kernel 0: reset counters (graph replays!) ----------------
__global__ void zero_cnt_kernel() {
    if (threadIdx.x < NE) g_cnt[threadIdx.x] = 0;
}

// ---------------- kernel 1: router (logits -> softmax -> top2 -> renorm -> lists) --------
__global__ void router_kernel(const float* __restrict__ x,
                              const float* __restrict__ rw) {
    int t = blockIdx.x;
    int warp = threadIdx.x >> 5, lane = threadIdx.x & 31;
    const float* xr = x + (size_t)t * HD;
    const float* wr = rw + (size_t)warp * HD;
    float s = 0.f;
    for (int i = lane; i < HD; i += 32) s = fmaf(xr[i], wr[i], s);
    #pragma unroll
    for (int o = 16; o; o >>= 1) s += __shfl_xor_sync(0xffffffffu, s, o);
    __shared__ float lg[NE];
    if (lane == 0) lg[warp] = s;
    __syncthreads();
    if (threadIdx.x == 0) {
        float mx = lg[0];
        #pragma unroll
        for (int i = 1; i < NE; i++) mx = fmaxf(mx, lg[i]);
        float p[NE];
        #pragma unroll
        for (int i = 0; i < NE; i++) p[i] = expf(lg[i] - mx);
        // top-2 (stable: first occurrence wins ties, matches jax top_k)
        int i0 = 0;
        #pragma unroll
        for (int i = 1; i < NE; i++) if (p[i] > p[i0]) i0 = i;
        int i1 = -1;
        #pragma unroll
        for (int i = 0; i < NE; i++) {
            if (i == i0) continue;
            if (i1 < 0 || p[i] > p[i1]) i1 = i;
        }
        float denom = p[i0] + p[i1];
        float w0 = p[i0] / denom, w1 = p[i1] / denom;
        int s0 = atomicAdd(&g_cnt[i0], 1);
        g_tok[i0][s0] = t; g_wt[i0][s0] = w0; g_slot[t][0] = i0 * NT + s0;
        int s1 = atomicAdd(&g_cnt[i1], 1);
        g_tok[i1][s1] = t; g_wt[i1][s1] = w1; g_slot[t][1] = i1 * NT + s1;
    }
}

// ---------------- kernel 2: fused gate/up GEMM + silu + weight fold ----------------
// h[e, m, n] = w[e,m] * silu(x[tok]·gateW[e,n]) * (x[tok]·upW[e,n])
__global__ __launch_bounds__(256) void gateup_kernel(
    const float* __restrict__ x,
    const float* __restrict__ gw,
    const float* __restrict__ uw)
{
    int e = blockIdx.z;
    int cnt = g_cnt[e];
    int m0 = blockIdx.y * BM;
    if (m0 >= cnt) return;
    int n0 = blockIdx.x * BN;

    __shared__ float As[BK][BM];
    __shared__ float Gs[BK][BN];
    __shared__ float Us[BK][BN];

    int tid = threadIdx.x;
    int tx = tid & 15, ty = tid >> 4;
    int lr = tid & 63;            // row within 64 (conflict-free STS)
    int lc = (tid >> 6) * 4;      // k-chunk

    int la0 = m0 + lr, la1 = m0 + lr + 64;
    int t0 = (la0 < cnt) ? g_tok[e][la0] : 0;
    int t1 = (la1 < cnt) ? g_tok[e][la1] : 0;
    const float* ap0 = x + (size_t)t0 * HD + lc;
    const float* ap1 = x + (size_t)t1 * HD + lc;
    const float* gp  = gw + ((size_t)e * ID + n0 + lr) * HD + lc;
    const float* up  = uw + ((size_t)e * ID + n0 + lr) * HD + lc;

    float accg[TM][TN] = {}, accu[TM][TN] = {};

    float4 ra0 = *(const float4*)ap0;
    float4 ra1 = *(const float4*)ap1;
    float4 rg  = *(const float4*)gp;
    float4 ru  = *(const float4*)up;

    for (int k0 = 0; k0 < HD; k0 += BK) {
        __syncthreads();
        As[lc+0][lr]    = ra0.x; As[lc+1][lr]    = ra0.y; As[lc+2][lr]    = ra0.z; As[lc+3][lr]    = ra0.w;
        As[lc+0][lr+64] = ra1.x; As[lc+1][lr+64] = ra1.y; As[lc+2][lr+64] = ra1.z; As[lc+3][lr+64] = ra1.w;
        Gs[lc+0][lr] = rg.x; Gs[lc+1][lr] = rg.y; Gs[lc+2][lr] = rg.z; Gs[lc+3][lr] = rg.w;
        Us[lc+0][lr] = ru.x; Us[lc+1][lr] = ru.y; Us[lc+2][lr] = ru.z; Us[lc+3][lr] = ru.w;
        __syncthreads();
        int kn = k0 + BK;
        if (kn < HD) {             // software-pipelined prefetch (hidden behind math)
            ra0 = *(const float4*)(ap0 + kn);
            ra1 = *(const float4*)(ap1 + kn);
            rg  = *(const float4*)(gp + kn);
            ru  = *(const float4*)(up + kn);
        }
        #pragma unroll
        for (int kk = 0; kk < BK; kk++) {
            float4 av0 = *(const float4*)&As[kk][ty * TM];
            float4 av1 = *(const float4*)&As[kk][ty * TM + 4];
            float4 bg  = *(const float4*)&Gs[kk][tx * TN];
            float4 bu  = *(const float4*)&Us[kk][tx * TN];
            float a[TM]   = {av0.x, av0.y, av0.z, av0.w, av1.x, av1.y, av1.z, av1.w};
            float bgv[TN] = {bg.x, bg.y, bg.z, bg.w};
            float buv[TN] = {bu.x, bu.y, bu.z, bu.w};
            #pragma unroll
            for (int i = 0; i < TM; i++) {
                #pragma unroll
                for (int j = 0; j < TN; j++) {
                    accg[i][j] = fmaf(a[i], bgv[j], accg[i][j]);
                    accu[i][j] = fmaf(a[i], buv[j], accu[i][j]);
                }
            }
        }
    }

    #pragma unroll
    for (int i = 0; i < TM; i++) {
        int lm = m0 + ty * TM + i;
        if (lm >= cnt) continue;
        float wt = g_wt[e][lm];
        float* hp = g_h + ((size_t)e * NT + lm) * ID + n0 + tx * TN;
        float4 o;
        {
            float g = accg[i][0]; float sg = g / (1.f + expf(-g)); o.x = wt * sg * accu[i][0];
            g = accg[i][1]; sg = g / (1.f + expf(-g)); o.y = wt * sg * accu[i][1];
            g = accg[i][2]; sg = g / (1.f + expf(-g)); o.z = wt * sg * accu[i][2];
            g = accg[i][3]; sg = g / (1.f + expf(-g)); o.w = wt * sg * accu[i][3];
        }
        *(float4*)hp = o;
    }
}

// ---------------- kernel 3: down GEMM:  y[e, m, n] = h[e,m,:] · downW[e,n,:] ----------------
__global__ __launch_bounds__(256) void down_kernel(const float* __restrict__ dw)
{
    int e = blockIdx.z;
    int cnt = g_cnt[e];
    int m0 = blockIdx.y * BM;
    if (m0 >= cnt) return;
    int n0 = blockIdx.x * BN;

    __shared__ float As[BK][BM];
    __shared__ float Bs[BK][BN];

    int tid = threadIdx.x;
    int tx = tid & 15, ty = tid >> 4;
    int lr = tid & 63;
    int lc = (tid >> 6) * 4;

    const float* ap0 = g_h + ((size_t)e * NT + m0 + lr) * ID + lc;
    const float* ap1 = ap0 + (size_t)64 * ID;
    const float* bp  = dw + ((size_t)e * HD + n0 + lr) * ID + lc;

    float acc[TM][TN] = {};

    float4 ra0 = *(const float4*)ap0;
    float4 ra1 = *(const float4*)ap1;
    float4 rb  = *(const float4*)bp;

    for (int k0 = 0; k0 < ID; k0 += BK) {
        __syncthreads();
        As[lc+0][lr]    = ra0.x; As[lc+1][lr]    = ra0.y; As[lc+2][lr]    = ra0.z; As[lc+3][lr]    = ra0.w;
        As[lc+0][lr+64] = ra1.x; As[lc+1][lr+64] = ra1.y; As[lc+2][lr+64] = ra1.z; As[lc+3][lr+64] = ra1.w;
        Bs[lc+0][lr] = rb.x; Bs[lc+1][lr] = rb.y; Bs[lc+2][lr] = rb.z; Bs[lc+3][lr] = rb.w;
        __syncthreads();
        int kn = k0 + BK;
        if (kn < ID) {
            ra0 = *(const float4*)(ap0 + kn);
            ra1 = *(const float4*)(ap1 + kn);
            rb  = *(const float4*)(bp + kn);
        }
        #pragma unroll
        for (int kk = 0; kk < BK; kk++) {
            float4 av0 = *(const float4*)&As[kk][ty * TM];
            float4 av1 = *(const float4*)&As[kk][ty * TM + 4];
            float4 bv  = *(const float4*)&Bs[kk][tx * TN];
            float a[TM]  = {av0.x, av0.y, av0.z, av0.w, av1.x, av1.y, av1.z, av1.w};
            float b[TN]  = {bv.x, bv.y, bv.z, bv.w};
            #pragma unroll
            for (int i = 0; i < TM; i++) {
                #pragma unroll
                for (int j = 0; j < TN; j++)
                    acc[i][j] = fmaf(a[i], b[j], acc[i][j]);
            }
        }
    }

    #pragma unroll
    for (int i = 0; i < TM; i++) {
        int lm = m0 + ty * TM + i;
        if (lm >= cnt) continue;
        float* yp = g_y + ((size_t)e * NT + lm) * HD + n0 + tx * TN;
        float4 o = {acc[i][0], acc[i][1], acc[i][2], acc[i][3]};
        *(float4*)yp = o;
    }
}

// ---------------- kernel 4: combine the token's two expert rows ----------------
__global__ void combine_kernel(float* __restrict__ out) {
    int t = blockIdx.x;
    int s0 = g_slot[t][0], s1 = g_slot[t][1];
    const float4* y0 = (const float4*)(g_y + (size_t)s0 * HD);
    const float4* y1 = (const float4*)(g_y + (size_t)s1 * HD);
    float4* o = (float4*)(out + (size_t)t * HD);
    int i = threadIdx.x;
    if (i < HD / 4) {
        float4 a = y0[i], b = y1[i];
        float4 r = {a.x + b.x, a.y + b.y, a.z + b.z, a.w + b.w};
        o[i] = r;
    }
}

// ---------------- launch ----------------
extern "C" void kernel_launch(void* const* d_in, const int* in_sizes, int n_in,
                              void* d_out, int out_size) {
    (void)in_sizes; (void)n_in; (void)out_size;
    const float* x  = (const float*)d_in[0];
    const float* rw = (const float*)d_in[1];
    const float* gw = (const float*)d_in[2];
    const float* uw = (const float*)d_in[3];
    const float* dw = (const float*)d_in[4];
    float* out = (float*)d_out;

    zero_cnt_kernel<<<1, 32>>>();
    router_kernel<<<NT, 128>>>(x, rw);

    dim3 g2(ID / BN, NT / BM, NE);
    gateup_kernel<<<g2, 256>>>(x, gw, uw);

    dim3 g3(HD / BN, NT / BM, NE);
    down_kernel<<<g3, 256>>>(dw);

    combine_kernel<<<NT, 224>>>(out);
}

// round 2
// speedup vs baseline: 1.0007x; 1.0007x over previous
#include <cuda_runtime.h>
#include <math.h>

// Problem dims
#define NT 4096   // B*S tokens
#define HD 896    // hidden
#define ID 4864   // intermediate
#define NE 4      // experts
// GEMM tiling
#define BM 128
#define BN 64
#define BK 16
#define TM 8
#define TN 4

// ---------------- scratch (device globals; no allocation in kernel_launch) ----------------
__device__ int   g_cnt[NE];
__device__ int   g_tok[NE][NT];
__device__ float g_wt[NE][NT];
__device__ int   g_slot[NT][2];
__device__ float g_h[(size_t)NE * NT * ID];   // silu(xG^T)*(xU^T)*w, per (expert, local slot)
__device__ float g_y[(size_t)NE * NT * HD];   // down-projected rows per (expert, local slot)

// ---------------- kernel 0: reset counters (graph replays!) ----------------
__global__ void zero_cnt_kernel() {
    if (threadIdx.x < NE) g_cnt[threadIdx.x] = 0;
}

// ---------------- kernel 1: router (logits -> softmax -> top2 -> renorm -> lists) --------
__global__ void router_kernel(const float* __restrict__ x,
                              const float* __restrict__ rw) {
    int t = blockIdx.x;
    int warp = threadIdx.x >> 5, lane = threadIdx.x & 31;
    const float* xr = x + (size_t)t * HD;
    const float* wr = rw + (size_t)warp * HD;
    float s = 0.f;
    for (int i = lane; i < HD; i += 32) s = fmaf(xr[i], wr[i], s);
    #pragma unroll
    for (int o = 16; o; o >>= 1) s += __shfl_xor_sync(0xffffffffu, s, o);
    __shared__ float lg[NE];
    if (lane == 0) lg[warp] = s;
    __syncthreads();
    if (threadIdx.x == 0) {
        float mx = lg[0];
        #pragma unroll
        for (int i = 1; i < NE; i++) mx = fmaxf(mx, lg[i]);
        float p[NE];
        #pragma unroll
        for (int i = 0; i < NE; i++) p[i] = expf(lg[i] - mx);
        // top-2 (stable: first occurrence wins ties, matches jax top_k)
        int i0 = 0;
        #pragma unroll
        for (int i = 1; i < NE; i++) if (p[i] > p[i0]) i0 = i;
        int i1 = -1;
        #pragma unroll
        for (int i = 0; i < NE; i++) {
            if (i == i0) continue;
            if (i1 < 0 || p[i] > p[i1]) i1 = i;
        }
        float denom = p[i0] + p[i1];
        float w0 = p[i0] / denom, w1 = p[i1] / denom;
        int s0 = atomicAdd(&g_cnt[i0], 1);
        g_tok[i0][s0] = t; g_wt[i0][s0] = w0; g_slot[t][0] = i0 * NT + s0;
        int s1 = atomicAdd(&g_cnt[i1], 1);
        g_tok[i1][s1] = t; g_wt[i1][s1] = w1; g_slot[t][1] = i1 * NT + s1;
    }
}

// ---------------- kernel 2: fused gate/up GEMM + silu + weight fold ----------------
// h[e, m, n] = w[e,m] * silu(x[tok]·gateW[e,n]) * (x[tok]·upW[e,n])
__global__ __launch_bounds__(256) void gateup_kernel(
    const float* __restrict__ x,
    const float* __restrict__ gw,
    const float* __restrict__ uw)
{
    int e = blockIdx.z;
    int cnt = g_cnt[e];
    int m0 = blockIdx.y * BM;
    if (m0 >= cnt) return;
    int n0 = blockIdx.x * BN;

    __shared__ float As[BK][BM];
    __shared__ float Gs[BK][BN];
    __shared__ float Us[BK][BN];

    int tid = threadIdx.x;
    int tx = tid & 15, ty = tid >> 4;
    int lr = tid & 63;            // row within 64 (conflict-free STS)
    int lc = (tid >> 6) * 4;      // k-chunk

    int la0 = m0 + lr, la1 = m0 + lr + 64;
    int t0 = (la0 < cnt) ? g_tok[e][la0] : 0;
    int t1 = (la1 < cnt) ? g_tok[e][la1] : 0;
    const float* ap0 = x + (size_t)t0 * HD + lc;
    const float* ap1 = x + (size_t)t1 * HD + lc;
    const float* gp  = gw + ((size_t)e * ID + n0 + lr) * HD + lc;
    const float* up  = uw + ((size_t)e * ID + n0 + lr) * HD + lc;

    float accg[TM][TN] = {}, accu[TM][TN] = {};

    float4 ra0 = *(const float4*)ap0;
    float4 ra1 = *(const float4*)ap1;
    float4 rg  = *(const float4*)gp;
    float4 ru  = *(const float4*)up;

    for (int k0 = 0; k0 < HD; k0 += BK) {
        __syncthreads();
        As[lc+0][lr]    = ra0.x; As[lc+1][lr]    = ra0.y; As[lc+2][lr]    = ra0.z; As[lc+3][lr]    = ra0.w;
        As[lc+0][lr+64] = ra1.x; As[lc+1][lr+64] = ra1.y; As[lc+2][lr+64] = ra1.z; As[lc+3][lr+64] = ra1.w;
        Gs[lc+0][lr] = rg.x; Gs[lc+1][lr] = rg.y; Gs[lc+2][lr] = rg.z; Gs[lc+3][lr] = rg.w;
        Us[lc+0][lr] = ru.x; Us[lc+1][lr] = ru.y; Us[lc+2][lr] = ru.z; Us[lc+3][lr] = ru.w;
        __syncthreads();
        int kn = k0 + BK;
        if (kn < HD) {             // software-pipelined prefetch (hidden behind math)
            ra0 = *(const float4*)(ap0 + kn);
            ra1 = *(const float4*)(ap1 + kn);
            rg  = *(const float4*)(gp + kn);
            ru  = *(const float4*)(up + kn);
        }
        #pragma unroll
        for (int kk = 0; kk < BK; kk++) {
            float4 av0 = *(const float4*)&As[kk][ty * TM];
            float4 av1 = *(const float4*)&As[kk][ty * TM + 4];
            float4 bg  = *(const float4*)&Gs[kk][tx * TN];
            float4 bu  = *(const float4*)&Us[kk][tx * TN];
            float a[TM]   = {av0.x, av0.y, av0.z, av0.w, av1.x, av1.y, av1.z, av1.w};
            float bgv[TN] = {bg.x, bg.y, bg.z, bg.w};
            float buv[TN] = {bu.x, bu.y, bu.z, bu.w};
            #pragma unroll
            for (int i = 0; i < TM; i++) {
                #pragma unroll
                for (int j = 0; j < TN; j++) {
                    accg[i][j] = fmaf(a[i], bgv[j], accg[i][j]);
                    accu[i][j] = fmaf(a[i], buv[j], accu[i][j]);
                }
            }
        }
    }

    #pragma unroll
    for (int i = 0; i < TM; i++) {
        int lm = m0 + ty * TM + i;
        if (lm >= cnt) continue;
        float wt = g_wt[e][lm];
        float* hp = g_h + ((size_t)e * NT + lm) * ID + n0 + tx * TN;
        float4 o;
        {
            float g = accg[i][0]; float sg = g / (1.f + expf(-g)); o.x = wt * sg * accu[i][0];
            g = accg[i][1]; sg = g / (1.f + expf(-g)); o.y = wt * sg * accu[i][1];
            g = accg[i][2]; sg = g / (1.f + expf(-g)); o.z = wt * sg * accu[i][2];
            g = accg[i][3]; sg = g / (1.f + expf(-g)); o.w = wt * sg * accu[i][3];
        }
        *(float4*)hp = o;
    }
}

// ---------------- kernel 3: down GEMM:  y[e, m, n] = h[e,m,:] · downW[e,n,:] ----------------
__global__ __launch_bounds__(256) void down_kernel(const float* __restrict__ dw)
{
    int e = blockIdx.z;
    int cnt = g_cnt[e];
    int m0 = blockIdx.y * BM;
    if (m0 >= cnt) return;
    int n0 = blockIdx.x * BN;

    __shared__ float As[BK][BM];
    __shared__ float Bs[BK][BN];

    int tid = threadIdx.x;
    int tx = tid & 15, ty = tid >> 4;
    int lr = tid & 63;
    int lc = (tid >> 6) * 4;

    const float* ap0 = g_h + ((size_t)e * NT + m0 + lr) * ID + lc;
    const float* ap1 = ap0 + (size_t)64 * ID;
    const float* bp  = dw + ((size_t)e * HD + n0 + lr) * ID + lc;

    float acc[TM][TN] = {};

    float4 ra0 = *(const float4*)ap0;
    float4 ra1 = *(const float4*)ap1;
    float4 rb  = *(const float4*)bp;

    for (int k0 = 0; k0 < ID; k0 += BK) {
        __syncthreads();
        As[lc+0][lr]    = ra0.x; As[lc+1][lr]    = ra0.y; As[lc+2][lr]    = ra0.z; As[lc+3][lr]    = ra0.w;
        As[lc+0][lr+64] = ra1.x; As[lc+1][lr+64] = ra1.y; As[lc+2][lr+64] = ra1.z; As[lc+3][lr+64] = ra1.w;
        Bs[lc+0][lr] = rb.x; Bs[lc+1][lr] = rb.y; Bs[lc+2][lr] = rb.z; Bs[lc+3][lr] = rb.w;
        __syncthreads();
        int kn = k0 + BK;
        if (kn < ID) {
            ra0 = *(const float4*)(ap0 + kn);
            ra1 = *(const float4*)(ap1 + kn);
            rb  = *(const float4*)(bp + kn);
        }
        #pragma unroll
        for (int kk = 0; kk < BK; kk++) {
            float4 av0 = *(const float4*)&As[kk][ty * TM];
            float4 av1 = *(const float4*)&As[kk][ty * TM + 4];
            float4 bv  = *(const float4*)&Bs[kk][tx * TN];
            float a[TM]  = {av0.x, av0.y, av0.z, av0.w, av1.x, av1.y, av1.z, av1.w};
            float b[TN]  = {bv.x, bv.y, bv.z, bv.w};
            #pragma unroll
            for (int i = 0; i < TM; i++) {
                #pragma unroll
                for (int j = 0; j < TN; j++)
                    acc[i][j] = fmaf(a[i], b[j], acc[i][j]);
            }
        }
    }

    #pragma unroll
    for (int i = 0; i < TM; i++) {
        int lm = m0 + ty * TM + i;
        if (lm >= cnt) continue;
        float* yp = g_y + ((size_t)e * NT + lm) * HD + n0 + tx * TN;
        float4 o = {acc[i][0], acc[i][1], acc[i][2], acc[i][3]};
        *(float4*)yp = o;
    }
}

// ---------------- kernel 4: combine the token's two expert rows ----------------
__global__ void combine_kernel(float* __restrict__ out) {
    int t = blockIdx.x;
    int s0 = g_slot[t][0], s1 = g_slot[t][1];
    const float4* y0 = (const float4*)(g_y + (size_t)s0 * HD);
    const float4* y1 = (const float4*)(g_y + (size_t)s1 * HD);
    float4* o = (float4*)(out + (size_t)t * HD);
    int i = threadIdx.x;
    if (i < HD / 4) {
        float4 a = y0[i], b = y1[i];
        float4 r = {a.x + b.x, a.y + b.y, a.z + b.z, a.w + b.w};
        o[i] = r;
    }
}

// ---------------- launch ----------------
extern "C" void kernel_launch(void* const* d_in, const int* in_sizes, int n_in,
                              void* d_out, int out_size) {
    (void)in_sizes; (void)n_in; (void)out_size;
    const float* x  = (const float*)d_in[0];
    const float* rw = (const float*)d_in[1];
    const float* gw = (const float*)d_in[2];
    const float* uw = (const float*)d_in[3];
    const float* dw = (const float*)d_in[4];
    float* out = (float*)d_out;

    zero_cnt_kernel<<<1, 32>>>();
    router_kernel<<<NT, 128>>>(x, rw);

    dim3 g2(ID / BN, NT / BM, NE);
    gateup_kernel<<<g2, 256>>>(x, gw, uw);

    dim3 g3(HD / BN, NT / BM, NE);
    down_kernel<<<g3, 256>>>(dw);

    combine_kernel<<<NT, 224>>>(out);
}